// round 3
// baseline (speedup 1.0000x reference)
#include <cuda_runtime.h>
#include <cstdint>

// Problem shape (fixed by the dataset):
//   input    f32 [B=4, C=64, H=512, W=512]
//   gathered f32 [N=2048, C=64, kh=16, kw=16]
//   indices  (b, h_block, w_block) per row; dtype int32 (JAX x64 disabled) or
//            int64 — detected at runtime on device.
//
// stride == kernel == 16, so patches tile the image into 4096 disjoint 16x16
// slots; only duplicate indices overlap. Build per-slot linked lists of patch
// ids (atomicExch, tiny), then one streaming pass:
//   out = in + sum(patches in this element's slot)
// Traffic ~= 256MB (in) + 128MB (gathered) + 256MB (out) = 640MB, no atomics
// on the hot path, fully float4-coalesced.

#define BB 4
#define CC 64
#define HH 512
#define WW 512
#define NN 2048
#define NSLOTS 4096   // BB * (HH/16) * (WW/16)

__device__ int g_head[NSLOTS];
__device__ int g_next[NN];
__device__ int g_is64;

__global__ void init_heads_kernel() {
    int i = blockIdx.x * blockDim.x + threadIdx.x;
    if (i == 0) g_is64 = 1;
    if (i < NSLOTS) g_head[i] = -1;
}

// Detect index dtype. Read first 3072 uint64 words = 24576 bytes, which is
// exactly the full buffer if int32 (N*3*4) and half if int64 (N*3*8) — safe
// either way. True int64 indices are all < 512 -> high word always 0.
// int32 data read as int64 packs the next field into the high word, which is
// nonzero somewhere with probability 1 - 32^-1024.
__global__ void detect_dtype_kernel(const unsigned long long* __restrict__ w) {
    int i = blockIdx.x * blockDim.x + threadIdx.x;   // 3072 threads
    if (i < 3072 && (w[i] >> 32) != 0ull) g_is64 = 0;
}

__global__ void build_lists_kernel(const void* __restrict__ idx_raw) {
    int n = blockIdx.x * blockDim.x + threadIdx.x;
    if (n >= NN) return;
    int b, hb, wb;
    if (g_is64) {
        const long long* idx = (const long long*)idx_raw;
        b  = (int)idx[3 * n + 0];
        hb = (int)idx[3 * n + 1];
        wb = (int)idx[3 * n + 2];
    } else {
        const int* idx = (const int*)idx_raw;
        b  = idx[3 * n + 0];
        hb = idx[3 * n + 1];
        wb = idx[3 * n + 2];
    }
    int slot = (b << 10) | (hb << 5) | wb;
    g_next[n] = atomicExch(&g_head[slot & (NSLOTS - 1)], n);
}

// One thread per float4 of the output. 67,108,864 floats -> 16,777,216 float4.
__global__ void __launch_bounds__(256) scatter_main_kernel(
    const float4* __restrict__ in4,
    const float4* __restrict__ g4,
    float4* __restrict__ out4)
{
    unsigned i4 = blockIdx.x * blockDim.x + threadIdx.x;  // < 2^24

    // linear index decomposition (all powers of 2)
    unsigned w4 = i4 & 127u;          // float4 column: w = w4*4
    unsigned h  = (i4 >> 7) & 511u;
    unsigned c  = (i4 >> 16) & 63u;
    unsigned b  = i4 >> 22;

    unsigned slot = (b << 10) | ((h >> 4) << 5) | (w4 >> 2);

    float4 val = in4[i4];

    int p = g_head[slot];
    if (p >= 0) {
        // patch element (float4 units): p*4096 + c*64 + (h&15)*4 + (w4&3)
        unsigned local = (c << 6) | ((h & 15u) << 2) | (w4 & 3u);
        do {
            float4 g = g4[((unsigned)p << 12) + local];
            val.x += g.x; val.y += g.y; val.z += g.z; val.w += g.w;
            p = g_next[p];
        } while (p >= 0);
    }

    out4[i4] = val;
}

extern "C" void kernel_launch(void* const* d_in, const int* in_sizes, int n_in,
                              void* d_out, int out_size) {
    const float* input    = (const float*)d_in[0];
    const float* gathered = (const float*)d_in[1];
    const void*  indices  = d_in[2];
    float* out = (float*)d_out;

    init_heads_kernel<<<(NSLOTS + 255) / 256, 256>>>();
    detect_dtype_kernel<<<(3072 + 255) / 256, 256>>>(
        (const unsigned long long*)indices);
    build_lists_kernel<<<(NN + 255) / 256, 256>>>(indices);

    const unsigned total4 = (unsigned)(BB * CC * HH * WW) / 4u;  // 16,777,216
    scatter_main_kernel<<<total4 / 256, 256>>>(
        (const float4*)input, (const float4*)gathered, (float4*)out);
}